// round 13
// baseline (speedup 1.0000x reference)
#include <cuda_runtime.h>
#include <cuda_fp16.h>
#include <cuda_bf16.h>
#include <math.h>
#include <stdint.h>

// Problem dims
#define TT   128
#define BB   256
#define NN   (TT*BB)        // 32768
#define HID  128
#define G4   512            // 4*HID
#define NFLAT 1024
#define NA   7

// NOTE (R10 finding): this harness emits compute_103 PTX; ptxas rejects ALL
// tcgen05/.kind::tf32 instructions on plain sm_103. mma.sync is the tensor
// ceiling reachable here; fp16 m16n8k16 is its fastest shape (2x tf32 k8).

// ---------------- scratch (device globals, no allocation) ----------------
__device__ __align__(16) __half g_feat[NN * NFLAT];  // fp16 feat (67 MB)
__device__ __align__(16) float  g_pre [NN * G4];
__device__ __align__(16) __half g_wih [G4 * NFLAT];  // fp16 weights (1 MB)
__device__ __align__(16) float  g_bias[G4];

__device__ __forceinline__ unsigned f2tf(float f) {
    unsigned u;
    asm("cvt.rna.tf32.f32 %0, %1;" : "=r"(u) : "f"(f));
    return u;
}
__device__ __forceinline__ unsigned smem_u32(const void* p) {
    unsigned r;
    asm("{ .reg .u64 t; cvta.to.shared.u64 t, %1; cvt.u32.u64 %0, t; }" : "=r"(r) : "l"(p));
    return r;
}
// MUFU-based tanh, overflow-safe
__device__ __forceinline__ float fast_tanh(float x) {
    float t = __expf(-2.f * fabsf(x));
    float r = __fdividef(1.f - t, 1.f + t);
    return copysignf(r, x);
}
__device__ __forceinline__ float fast_sigmoid(float x) {
    return __fdividef(1.f, 1.f + __expf(-x));
}

// ---------------- Kernel 0: prep (fp16 weights + fused bias) ----------------
__global__ __launch_bounds__(256) void prep_kernel(
    const float* __restrict__ wih,
    const float* __restrict__ bih, const float* __restrict__ bhh)
{
    int i = blockIdx.x * 256 + threadIdx.x;
    if (i < G4 * NFLAT / 4) {
        float4 v = *(const float4*)&wih[i * 4];
        __half2 h01 = __floats2half2_rn(v.x, v.y);
        __half2 h23 = __floats2half2_rn(v.z, v.w);
        uint2 pk;
        pk.x = *(unsigned*)&h01;
        pk.y = *(unsigned*)&h23;
        *(uint2*)&g_wih[i * 4] = pk;
    }
    if (i < G4) g_bias[i] = bih[i] + bhh[i];
}

// ---------------- Kernel 1: conv stack; conv3 via tf32 mma; fp16 feat out ----------------
#define CV_XS 0
#define CV_C1 588
#define CV_S1 577
#define CV_C2 2896
#define CV_S2 801
#define CV_W2 6100
#define CV_A  8148
#define CV_B  16596
#define CV_SMEM_FLOATS (CV_B + 64*132)
#define CV_SMEM_BYTES  (CV_SMEM_FLOATS * 4)   // ~100 KB

__global__ __launch_bounds__(256) void conv_feat_kernel(
    const float* __restrict__ obs,
    const float* __restrict__ w1, const float* __restrict__ b1,
    const float* __restrict__ w2, const float* __restrict__ b2,
    const float* __restrict__ w3, const float* __restrict__ b3)
{
    extern __shared__ __align__(16) float sm[];
    const int tid = threadIdx.x;
    const int n0 = blockIdx.x * 4;

    {
        const float4* s2 = (const float4*)w2;
        float4* d2 = (float4*)(sm + CV_W2);
        for (int i = tid; i < 32*16; i += 256) d2[i] = s2[i];
        for (int i = tid; i < 64*128; i += 256) {
            int o = i >> 7, col = i & 127;
            sm[CV_B + o*132 + col] = __uint_as_float(f2tf(w3[i]));
        }
    }
    for (int i = tid; i < 4*147; i += 256) {
        int s = i / 147, r = i % 147;
        int h = r / 21, q = r % 21, w = q / 3, c = q % 3;
        sm[CV_XS + s*147 + c*49 + h*7 + w] = obs[(size_t)n0 * 147 + i];
    }
    __syncthreads();

    // conv1: 16 x 6x6, 3ch 2x2 (fp32)
    for (int i = tid; i < 4*576; i += 256) {
        int s = i / 576, r = i % 576;
        int o = r / 36, q = r % 36, y = q / 6, x = q % 6;
        float acc = __ldg(&b1[o]);
        #pragma unroll
        for (int c = 0; c < 3; c++) {
            float4 wv = *(const float4*)&w1[(o*3 + c) * 4];
            const float* xb = sm + CV_XS + s*147 + c*49 + y*7 + x;
            acc += xb[0] * wv.x + xb[1] * wv.y + xb[7] * wv.z + xb[8] * wv.w;
        }
        sm[CV_C1 + s*CV_S1 + o*36 + y*6 + x] = fmaxf(acc, 0.f);
    }
    __syncthreads();

    // conv2: 32 x 5x5, 16ch 2x2 (fp32)
    if (tid < 200) {
        int oh = tid / 100, rem = tid % 100;
        int pos = rem >> 2, s = rem & 3;
        int y = pos / 5, x = pos % 5;
        int o0 = oh * 16;
        float acc[16];
        #pragma unroll
        for (int o = 0; o < 16; o++) acc[o] = __ldg(&b2[o0 + o]);
        const float4* w2v = (const float4*)(sm + CV_W2);
        #pragma unroll 4
        for (int c = 0; c < 16; c++) {
            const float* xb = sm + CV_C1 + s*CV_S1 + c*36 + y*6 + x;
            float aa = xb[0], ab = xb[1], ac = xb[6], ad = xb[7];
            #pragma unroll
            for (int o = 0; o < 16; o++) {
                float4 wv = w2v[(o0 + o)*16 + c];
                acc[o] += aa*wv.x + ab*wv.y + ac*wv.z + ad*wv.w;
            }
        }
        #pragma unroll
        for (int o = 0; o < 16; o++)
            sm[CV_C2 + s*CV_S2 + (o0 + o)*25 + pos] = fmaxf(acc[o], 0.f);
    }
    __syncthreads();

    // im2col for conv3
    for (int i = tid; i < 64*128; i += 256) {
        int row = i >> 7, col = i & 127;
        int s = row >> 4, pos = row & 15, y = pos >> 2, x = pos & 3;
        int c = col >> 2, j = col & 3, dy = j >> 1, dx = j & 1;
        float v = sm[CV_C2 + s*CV_S2 + c*25 + (y+dy)*5 + (x+dx)];
        sm[CV_A + row*132 + col] = __uint_as_float(f2tf(v));
    }
    __syncthreads();

    // conv3 mma: [64x64] = A[64x128] @ B^T, m16n8k8 tf32 -> fp16 feat
    {
        const int lane = tid & 31, wid = tid >> 5;
        const int lr = lane >> 2, lc = lane & 3;
        const int wm = wid & 1, wn = wid >> 1;
        const unsigned* As = (const unsigned*)(sm + CV_A);
        const unsigned* Bs = (const unsigned*)(sm + CV_B);

        float acc[2][2][4];
        #pragma unroll
        for (int mt = 0; mt < 2; mt++)
            #pragma unroll
            for (int nt = 0; nt < 2; nt++)
                #pragma unroll
                for (int r = 0; r < 4; r++) acc[mt][nt][r] = 0.f;

        #pragma unroll 4
        for (int ks = 0; ks < 16; ks++) {
            const int k0 = ks * 8;
            unsigned a[2][4], b[2][2];
            #pragma unroll
            for (int mt = 0; mt < 2; mt++) {
                int m0 = wm * 32 + mt * 16;
                a[mt][0] = As[(m0 + lr    ) * 132 + k0 + lc    ];
                a[mt][1] = As[(m0 + lr + 8) * 132 + k0 + lc    ];
                a[mt][2] = As[(m0 + lr    ) * 132 + k0 + lc + 4];
                a[mt][3] = As[(m0 + lr + 8) * 132 + k0 + lc + 4];
            }
            #pragma unroll
            for (int nt = 0; nt < 2; nt++) {
                int nr = wn * 16 + nt * 8;
                b[nt][0] = Bs[(nr + lr) * 132 + k0 + lc    ];
                b[nt][1] = Bs[(nr + lr) * 132 + k0 + lc + 4];
            }
            #pragma unroll
            for (int mt = 0; mt < 2; mt++)
                #pragma unroll
                for (int nt = 0; nt < 2; nt++) {
                    asm volatile(
                        "mma.sync.aligned.m16n8k8.row.col.f32.tf32.tf32.f32 "
                        "{%0,%1,%2,%3}, {%4,%5,%6,%7}, {%8,%9}, {%0,%1,%2,%3};\n"
                        : "+f"(acc[mt][nt][0]), "+f"(acc[mt][nt][1]),
                          "+f"(acc[mt][nt][2]), "+f"(acc[mt][nt][3])
                        : "r"(a[mt][0]), "r"(a[mt][1]), "r"(a[mt][2]), "r"(a[mt][3]),
                          "r"(b[nt][0]), "r"(b[nt][1]));
                }
        }

        #pragma unroll
        for (int mt = 0; mt < 2; mt++) {
            #pragma unroll
            for (int nt = 0; nt < 2; nt++) {
                int o = wn * 16 + nt * 8 + 2 * lc;
                float bo0 = __ldg(&b3[o]), bo1 = __ldg(&b3[o + 1]);
                #pragma unroll
                for (int rr = 0; rr < 2; rr++) {
                    int row = wm * 32 + mt * 16 + lr + rr * 8;
                    int s = row >> 4, pos = row & 15;
                    __half* fo = g_feat + (size_t)(n0 + s) * NFLAT;
                    float v0 = fmaxf(acc[mt][nt][rr * 2    ] + bo0, 0.f);
                    float v1 = fmaxf(acc[mt][nt][rr * 2 + 1] + bo1, 0.f);
                    fo[o * 16 + pos]       = __float2half_rn(v0);
                    fo[(o + 1) * 16 + pos] = __float2half_rn(v1);
                }
            }
        }
    }
}

// ---------------- Kernel 2: fp16 m16n8k16 GEMM, BK=32, 3-stage cp.async ----------------
// pre[N,512] = feat[N,1024] @ w_ih^T + bias. smem stride 40 halves (80 B):
// 16B-aligned chunks, fragment bank = (row*20 + lc) mod 32 (permutation).
#define GSTAGE 3
#define GSTRIDE_H (128*40)                    // halves per operand per stage
#define G_SMEM_BYTES (GSTAGE * 2 * GSTRIDE_H * 2)   // 61440 B; x2 CTAs = 120 KB

__global__ __launch_bounds__(256, 2) void gemm_pre_kernel()
{
    extern __shared__ __align__(16) __half smh[];
    __half* sA = smh;
    __half* sB = smh + GSTAGE * GSTRIDE_H;

    const int tid  = threadIdx.x;
    const int lane = tid & 31;
    const int wid  = tid >> 5;
    const int lr = lane >> 2, lc = lane & 3;
    const int wm = wid & 1;
    const int wn = wid >> 1;
    const int row0 = blockIdx.y * 128;
    const int col0 = blockIdx.x * 128;

    const unsigned baseA = smem_u32(sA);
    const unsigned baseB = smem_u32(sB);

    float acc[4][4][4];
    #pragma unroll
    for (int mt = 0; mt < 4; mt++)
        #pragma unroll
        for (int nt = 0; nt < 4; nt++)
            #pragma unroll
            for (int r = 0; r < 4; r++) acc[mt][nt][r] = 0.f;

    // staging: 128 rows x 32 halves per operand = 512x16B chunks each; 4/thread
    #define G_ISSUE(s, kt)                                                              \
    {                                                                                   \
        _Pragma("unroll")                                                               \
        for (int c = 0; c < 4; c++) {                                                   \
            int idx = tid + c * 256;                                                    \
            int isB = idx >> 9;                                                         \
            int m = (idx & 511) >> 2, kq = (idx & 3) * 8;                               \
            const __half* src = (isB ? g_wih + (size_t)(col0 + m) * NFLAT               \
                                     : g_feat + (size_t)(row0 + m) * NFLAT)             \
                                + (kt) + kq;                                            \
            unsigned dst = (isB ? baseB : baseA)                                        \
                           + ((s) * GSTRIDE_H + m * 40 + kq) * 2;                       \
            asm volatile("cp.async.cg.shared.global [%0], [%1], 16;"                    \
                         :: "r"(dst), "l"(src));                                        \
        }                                                                               \
    }

    G_ISSUE(0, 0);
    asm volatile("cp.async.commit_group;");
    G_ISSUE(1, 32);
    asm volatile("cp.async.commit_group;");

    const int NIT = NFLAT / 32;   // 32
    for (int it = 0; it < NIT; it++) {
        const int s = it % GSTAGE;
        asm volatile("cp.async.wait_group 1;");
        __syncthreads();
        if (it + 2 < NIT) {
            G_ISSUE((it + 2) % GSTAGE, (it + 2) * 32);
        }
        asm volatile("cp.async.commit_group;");

        const __half* pA = sA + s * GSTRIDE_H;
        const __half* pB = sB + s * GSTRIDE_H;
        #pragma unroll
        for (int ks = 0; ks < 2; ks++) {
            const int k0 = ks * 16;
            unsigned a[4][4], b[4][2];
            #pragma unroll
            for (int mt = 0; mt < 4; mt++) {
                int m0 = wm * 64 + mt * 16;
                a[mt][0] = *(const unsigned*)&pA[(m0 + lr    ) * 40 + k0 + 2*lc    ];
                a[mt][1] = *(const unsigned*)&pA[(m0 + lr + 8) * 40 + k0 + 2*lc    ];
                a[mt][2] = *(const unsigned*)&pA[(m0 + lr    ) * 40 + k0 + 2*lc + 8];
                a[mt][3] = *(const unsigned*)&pA[(m0 + lr + 8) * 40 + k0 + 2*lc + 8];
            }
            #pragma unroll
            for (int nt = 0; nt < 4; nt++) {
                int n0 = wn * 32 + nt * 8;
                b[nt][0] = *(const unsigned*)&pB[(n0 + lr) * 40 + k0 + 2*lc    ];
                b[nt][1] = *(const unsigned*)&pB[(n0 + lr) * 40 + k0 + 2*lc + 8];
            }
            #pragma unroll
            for (int mt = 0; mt < 4; mt++)
                #pragma unroll
                for (int nt = 0; nt < 4; nt++) {
                    asm volatile(
                        "mma.sync.aligned.m16n8k16.row.col.f32.f16.f16.f32 "
                        "{%0,%1,%2,%3}, {%4,%5,%6,%7}, {%8,%9}, {%0,%1,%2,%3};\n"
                        : "+f"(acc[mt][nt][0]), "+f"(acc[mt][nt][1]),
                          "+f"(acc[mt][nt][2]), "+f"(acc[mt][nt][3])
                        : "r"(a[mt][0]), "r"(a[mt][1]), "r"(a[mt][2]), "r"(a[mt][3]),
                          "r"(b[nt][0]), "r"(b[nt][1]));
                }
        }
    }

    float bb0[4], bb1[4];
    #pragma unroll
    for (int nt = 0; nt < 4; nt++) {
        int col = col0 + wn * 32 + nt * 8 + 2 * lc;
        bb0[nt] = g_bias[col];
        bb1[nt] = g_bias[col + 1];
    }
    #pragma unroll
    for (int mt = 0; mt < 4; mt++) {
        int r0 = row0 + wm * 64 + mt * 16 + lr;
        #pragma unroll
        for (int nt = 0; nt < 4; nt++) {
            int col = col0 + wn * 32 + nt * 8 + 2 * lc;
            *(float2*)&g_pre[(size_t)r0 * G4 + col] =
                make_float2(acc[mt][nt][0] + bb0[nt], acc[mt][nt][1] + bb1[nt]);
            *(float2*)&g_pre[(size_t)(r0 + 8) * G4 + col] =
                make_float2(acc[mt][nt][2] + bb0[nt], acc[mt][nt][3] + bb1[nt]);
        }
    }
}

// ---------------- Kernel 3: persistent LSTM + fused heads (R11-exact) ----------------
#define RC 64
__global__ __launch_bounds__(512, 1) void lstm_kernel(
    const float* __restrict__ done,
    const float* __restrict__ h0, const float* __restrict__ c0,
    const float* __restrict__ w_hh,
    const float* __restrict__ aw, const float* __restrict__ ab,
    const float* __restrict__ cw, const float* __restrict__ cb,
    float* __restrict__ out,
    float* __restrict__ hT, float* __restrict__ cT)
{
    __shared__ float hs[2][128];
    __shared__ float cs[2][128];
    __shared__ float gs[2][512];
    __shared__ float ho[2][2][128];     // [t&1][row][unit], unmasked h
    __shared__ float hw[8][128];        // rows 0-6 actor, row 7 critic
    __shared__ float hb[8];

    const int tid = threadIdx.x;
    const int b0  = blockIdx.x * 2;

    if (tid < 256) {
        int r = tid >> 7, u = tid & 127;
        float m = 1.f - done[b0 + r];
        hs[r][u] = h0[(b0 + r) * HID + u] * m;
        cs[r][u] = c0[(b0 + r) * HID + u] * m;
    }
    for (int i = tid; i < 8 * 128; i += 512) {
        int row = i >> 7, u = i & 127;
        hw[row][u] = (row < NA) ? aw[i] : cw[u];
    }
    if (tid < NA) hb[tid] = ab[tid];
    if (tid == NA) hb[NA] = cb[0];

    const float* wrow = w_hh + (size_t)tid * HID;
    float wc[RC];
    #pragma unroll
    for (int k = 0; k < RC; k++) wc[k] = wrow[k];
    __syncthreads();

    float a0 = g_pre[(size_t)b0 * G4 + tid];
    float a1 = g_pre[(size_t)(b0 + 1) * G4 + tid];

    for (int t = 0; t < TT; t++) {
        #pragma unroll
        for (int k = 0; k < RC; k++) {
            float w = wc[k];
            a0 = fmaf(w, hs[0][k], a0);
            a1 = fmaf(w, hs[1][k], a1);
        }
        #pragma unroll
        for (int k = RC; k < HID; k += 4) {
            float4 wv = *(const float4*)(wrow + k);
            a0 = fmaf(wv.x, hs[0][k], a0);   a0 = fmaf(wv.y, hs[0][k+1], a0);
            a0 = fmaf(wv.z, hs[0][k+2], a0); a0 = fmaf(wv.w, hs[0][k+3], a0);
            a1 = fmaf(wv.x, hs[1][k], a1);   a1 = fmaf(wv.y, hs[1][k+1], a1);
            a1 = fmaf(wv.z, hs[1][k+2], a1); a1 = fmaf(wv.w, hs[1][k+3], a1);
        }
        gs[0][tid] = a0;
        gs[1][tid] = a1;

        if (t + 1 < TT) {
            a0 = g_pre[((size_t)((t + 1) * BB + b0    )) * G4 + tid];
            a1 = g_pre[((size_t)((t + 1) * BB + b0 + 1)) * G4 + tid];
        }
        __syncthreads();

        if (tid < 256) {
            int r = tid >> 7, u = tid & 127;
            float ig = fast_sigmoid(gs[r][u]);
            float fg = fast_sigmoid(gs[r][128 + u]);
            float gg = fast_tanh(gs[r][256 + u]);
            float og = fast_sigmoid(gs[r][384 + u]);
            float c = fg * cs[r][u] + ig * gg;
            float h = og * fast_tanh(c);
            ho[t & 1][r][u] = h;
            float m = (t + 1 < TT) ? (1.f - done[(t + 1) * BB + b0 + r]) : 1.f;
            cs[r][u] = c * m;
            hs[r][u] = h * m;
        } else if (t > 0) {
            int tid2 = tid - 256;
            int r = tid2 >> 7, q = tid2 & 127;
            int col = q >> 4, seg = q & 15;
            const float* hv = ho[(t - 1) & 1][r] + seg * 8;
            const float* wv = hw[col] + seg * 8;
            float p = 0.f;
            #pragma unroll
            for (int j = 0; j < 8; j++) p = fmaf(hv[j], wv[j], p);
            #pragma unroll
            for (int off = 8; off >= 1; off >>= 1)
                p += __shfl_xor_sync(0xffffffffu, p, off);
            if (seg == 0)
                out[(size_t)((t - 1) * BB + b0 + r) * 8 + col] = p + hb[col];
        }
        __syncthreads();
    }

    if (tid < 256) {
        int r = tid >> 7, q = tid & 127;
        int col = q >> 4, seg = q & 15;
        const float* hv = ho[(TT - 1) & 1][r] + seg * 8;
        const float* wv = hw[col] + seg * 8;
        float p = 0.f;
        #pragma unroll
        for (int j = 0; j < 8; j++) p = fmaf(hv[j], wv[j], p);
        #pragma unroll
        for (int off = 8; off >= 1; off >>= 1)
            p += __shfl_xor_sync(0xffffffffu, p, off);
        if (seg == 0)
            out[(size_t)((TT - 1) * BB + b0 + r) * 8 + col] = p + hb[col];
    }

    if (tid < 256) {
        int r = tid >> 7, u = tid & 127;
        hT[(b0 + r) * HID + u] = hs[r][u];
        cT[(b0 + r) * HID + u] = cs[r][u];
    }
}

// ---------------- launch ----------------
extern "C" void kernel_launch(void* const* d_in, const int* in_sizes, int n_in,
                              void* d_out, int out_size)
{
    const float* obs   = (const float*)d_in[0];
    const float* done  = (const float*)d_in[1];
    const float* h0    = (const float*)d_in[2];
    const float* c0    = (const float*)d_in[3];
    const float* w1    = (const float*)d_in[4];
    const float* b1    = (const float*)d_in[5];
    const float* w2    = (const float*)d_in[6];
    const float* b2    = (const float*)d_in[7];
    const float* w3    = (const float*)d_in[8];
    const float* b3    = (const float*)d_in[9];
    const float* w_ih  = (const float*)d_in[10];
    const float* w_hh  = (const float*)d_in[11];
    const float* b_ih  = (const float*)d_in[12];
    const float* b_hh  = (const float*)d_in[13];
    const float* aw    = (const float*)d_in[14];
    const float* ab    = (const float*)d_in[15];
    const float* cw    = (const float*)d_in[16];
    const float* cb    = (const float*)d_in[17];

    float* out = (float*)d_out;                    // [N, 8]
    float* hT  = out + (size_t)NN * 8;             // [B, HID]
    float* cT  = hT + (size_t)BB * HID;            // [B, HID]

    static bool attr_done = false;
    if (!attr_done) {
        cudaFuncSetAttribute(conv_feat_kernel,
                             cudaFuncAttributeMaxDynamicSharedMemorySize,
                             CV_SMEM_BYTES);
        cudaFuncSetAttribute(gemm_pre_kernel,
                             cudaFuncAttributeMaxDynamicSharedMemorySize,
                             G_SMEM_BYTES);
        attr_done = true;
    }

    prep_kernel<<<(G4 * NFLAT / 4 + 255) / 256, 256>>>(w_ih, b_ih, b_hh);

    conv_feat_kernel<<<NN / 4, 256, CV_SMEM_BYTES>>>(obs, w1, b1, w2, b2, w3, b3);

    dim3 ggrid(G4 / 128, NN / 128);
    gemm_pre_kernel<<<ggrid, 256, G_SMEM_BYTES>>>();

    lstm_kernel<<<BB / 2, 512>>>(done, h0, c0, w_hh, aw, ab, cw, cb, out, hT, cT);
}

// round 14
// speedup vs baseline: 1.5072x; 1.5072x over previous
#include <cuda_runtime.h>
#include <cuda_fp16.h>
#include <cuda_bf16.h>
#include <math.h>
#include <stdint.h>

// Problem dims
#define TT   128
#define BB   256
#define NN   (TT*BB)        // 32768
#define HID  128
#define G4   512            // 4*HID
#define NFLAT 1024
#define NA   7

// R10 finding: harness emits compute_103 PTX; ptxas rejects tcgen05/.kind::tf32
// on plain sm_103 -> mma.sync is the tensor ceiling; fp16 m16n8k16 its best shape.
// R12 finding: identical lstm SASS ran 294->455us with HIGHER pipe% => DVFS
// throttle during that capture, not a kernel regression. This round re-benches
// the fp16 pipeline unchanged (A/A test of the throttle hypothesis).

// ---------------- scratch (device globals, no allocation) ----------------
__device__ __align__(16) __half g_feat[NN * NFLAT];  // fp16 feat (67 MB)
__device__ __align__(16) float  g_pre [NN * G4];
__device__ __align__(16) __half g_wih [G4 * NFLAT];  // fp16 weights (1 MB)
__device__ __align__(16) float  g_bias[G4];

__device__ __forceinline__ unsigned f2tf(float f) {
    unsigned u;
    asm("cvt.rna.tf32.f32 %0, %1;" : "=r"(u) : "f"(f));
    return u;
}
__device__ __forceinline__ unsigned smem_u32(const void* p) {
    unsigned r;
    asm("{ .reg .u64 t; cvta.to.shared.u64 t, %1; cvt.u32.u64 %0, t; }" : "=r"(r) : "l"(p));
    return r;
}
// MUFU-based tanh, overflow-safe
__device__ __forceinline__ float fast_tanh(float x) {
    float t = __expf(-2.f * fabsf(x));
    float r = __fdividef(1.f - t, 1.f + t);
    return copysignf(r, x);
}
__device__ __forceinline__ float fast_sigmoid(float x) {
    return __fdividef(1.f, 1.f + __expf(-x));
}

// ---------------- Kernel 0: prep (fp16 weights + fused bias) ----------------
__global__ __launch_bounds__(256) void prep_kernel(
    const float* __restrict__ wih,
    const float* __restrict__ bih, const float* __restrict__ bhh)
{
    int i = blockIdx.x * 256 + threadIdx.x;
    if (i < G4 * NFLAT / 4) {
        float4 v = *(const float4*)&wih[i * 4];
        __half2 h01 = __floats2half2_rn(v.x, v.y);
        __half2 h23 = __floats2half2_rn(v.z, v.w);
        uint2 pk;
        pk.x = *(unsigned*)&h01;
        pk.y = *(unsigned*)&h23;
        *(uint2*)&g_wih[i * 4] = pk;
    }
    if (i < G4) g_bias[i] = bih[i] + bhh[i];
}

// ---------------- Kernel 1: conv stack; conv3 via tf32 mma; fp16 feat out ----------------
#define CV_XS 0
#define CV_C1 588
#define CV_S1 577
#define CV_C2 2896
#define CV_S2 801
#define CV_W2 6100
#define CV_A  8148
#define CV_B  16596
#define CV_SMEM_FLOATS (CV_B + 64*132)
#define CV_SMEM_BYTES  (CV_SMEM_FLOATS * 4)   // ~100 KB

__global__ __launch_bounds__(256) void conv_feat_kernel(
    const float* __restrict__ obs,
    const float* __restrict__ w1, const float* __restrict__ b1,
    const float* __restrict__ w2, const float* __restrict__ b2,
    const float* __restrict__ w3, const float* __restrict__ b3)
{
    extern __shared__ __align__(16) float sm[];
    const int tid = threadIdx.x;
    const int n0 = blockIdx.x * 4;

    {
        const float4* s2 = (const float4*)w2;
        float4* d2 = (float4*)(sm + CV_W2);
        for (int i = tid; i < 32*16; i += 256) d2[i] = s2[i];
        for (int i = tid; i < 64*128; i += 256) {
            int o = i >> 7, col = i & 127;
            sm[CV_B + o*132 + col] = __uint_as_float(f2tf(w3[i]));
        }
    }
    for (int i = tid; i < 4*147; i += 256) {
        int s = i / 147, r = i % 147;
        int h = r / 21, q = r % 21, w = q / 3, c = q % 3;
        sm[CV_XS + s*147 + c*49 + h*7 + w] = obs[(size_t)n0 * 147 + i];
    }
    __syncthreads();

    // conv1: 16 x 6x6, 3ch 2x2 (fp32)
    for (int i = tid; i < 4*576; i += 256) {
        int s = i / 576, r = i % 576;
        int o = r / 36, q = r % 36, y = q / 6, x = q % 6;
        float acc = __ldg(&b1[o]);
        #pragma unroll
        for (int c = 0; c < 3; c++) {
            float4 wv = *(const float4*)&w1[(o*3 + c) * 4];
            const float* xb = sm + CV_XS + s*147 + c*49 + y*7 + x;
            acc += xb[0] * wv.x + xb[1] * wv.y + xb[7] * wv.z + xb[8] * wv.w;
        }
        sm[CV_C1 + s*CV_S1 + o*36 + y*6 + x] = fmaxf(acc, 0.f);
    }
    __syncthreads();

    // conv2: 32 x 5x5, 16ch 2x2 (fp32)
    if (tid < 200) {
        int oh = tid / 100, rem = tid % 100;
        int pos = rem >> 2, s = rem & 3;
        int y = pos / 5, x = pos % 5;
        int o0 = oh * 16;
        float acc[16];
        #pragma unroll
        for (int o = 0; o < 16; o++) acc[o] = __ldg(&b2[o0 + o]);
        const float4* w2v = (const float4*)(sm + CV_W2);
        #pragma unroll 4
        for (int c = 0; c < 16; c++) {
            const float* xb = sm + CV_C1 + s*CV_S1 + c*36 + y*6 + x;
            float aa = xb[0], ab = xb[1], ac = xb[6], ad = xb[7];
            #pragma unroll
            for (int o = 0; o < 16; o++) {
                float4 wv = w2v[(o0 + o)*16 + c];
                acc[o] += aa*wv.x + ab*wv.y + ac*wv.z + ad*wv.w;
            }
        }
        #pragma unroll
        for (int o = 0; o < 16; o++)
            sm[CV_C2 + s*CV_S2 + (o0 + o)*25 + pos] = fmaxf(acc[o], 0.f);
    }
    __syncthreads();

    // im2col for conv3
    for (int i = tid; i < 64*128; i += 256) {
        int row = i >> 7, col = i & 127;
        int s = row >> 4, pos = row & 15, y = pos >> 2, x = pos & 3;
        int c = col >> 2, j = col & 3, dy = j >> 1, dx = j & 1;
        float v = sm[CV_C2 + s*CV_S2 + c*25 + (y+dy)*5 + (x+dx)];
        sm[CV_A + row*132 + col] = __uint_as_float(f2tf(v));
    }
    __syncthreads();

    // conv3 mma: [64x64] = A[64x128] @ B^T, m16n8k8 tf32 -> fp16 feat
    {
        const int lane = tid & 31, wid = tid >> 5;
        const int lr = lane >> 2, lc = lane & 3;
        const int wm = wid & 1, wn = wid >> 1;
        const unsigned* As = (const unsigned*)(sm + CV_A);
        const unsigned* Bs = (const unsigned*)(sm + CV_B);

        float acc[2][2][4];
        #pragma unroll
        for (int mt = 0; mt < 2; mt++)
            #pragma unroll
            for (int nt = 0; nt < 2; nt++)
                #pragma unroll
                for (int r = 0; r < 4; r++) acc[mt][nt][r] = 0.f;

        #pragma unroll 4
        for (int ks = 0; ks < 16; ks++) {
            const int k0 = ks * 8;
            unsigned a[2][4], b[2][2];
            #pragma unroll
            for (int mt = 0; mt < 2; mt++) {
                int m0 = wm * 32 + mt * 16;
                a[mt][0] = As[(m0 + lr    ) * 132 + k0 + lc    ];
                a[mt][1] = As[(m0 + lr + 8) * 132 + k0 + lc    ];
                a[mt][2] = As[(m0 + lr    ) * 132 + k0 + lc + 4];
                a[mt][3] = As[(m0 + lr + 8) * 132 + k0 + lc + 4];
            }
            #pragma unroll
            for (int nt = 0; nt < 2; nt++) {
                int nr = wn * 16 + nt * 8;
                b[nt][0] = Bs[(nr + lr) * 132 + k0 + lc    ];
                b[nt][1] = Bs[(nr + lr) * 132 + k0 + lc + 4];
            }
            #pragma unroll
            for (int mt = 0; mt < 2; mt++)
                #pragma unroll
                for (int nt = 0; nt < 2; nt++) {
                    asm volatile(
                        "mma.sync.aligned.m16n8k8.row.col.f32.tf32.tf32.f32 "
                        "{%0,%1,%2,%3}, {%4,%5,%6,%7}, {%8,%9}, {%0,%1,%2,%3};\n"
                        : "+f"(acc[mt][nt][0]), "+f"(acc[mt][nt][1]),
                          "+f"(acc[mt][nt][2]), "+f"(acc[mt][nt][3])
                        : "r"(a[mt][0]), "r"(a[mt][1]), "r"(a[mt][2]), "r"(a[mt][3]),
                          "r"(b[nt][0]), "r"(b[nt][1]));
                }
        }

        #pragma unroll
        for (int mt = 0; mt < 2; mt++) {
            #pragma unroll
            for (int nt = 0; nt < 2; nt++) {
                int o = wn * 16 + nt * 8 + 2 * lc;
                float bo0 = __ldg(&b3[o]), bo1 = __ldg(&b3[o + 1]);
                #pragma unroll
                for (int rr = 0; rr < 2; rr++) {
                    int row = wm * 32 + mt * 16 + lr + rr * 8;
                    int s = row >> 4, pos = row & 15;
                    __half* fo = g_feat + (size_t)(n0 + s) * NFLAT;
                    float v0 = fmaxf(acc[mt][nt][rr * 2    ] + bo0, 0.f);
                    float v1 = fmaxf(acc[mt][nt][rr * 2 + 1] + bo1, 0.f);
                    fo[o * 16 + pos]       = __float2half_rn(v0);
                    fo[(o + 1) * 16 + pos] = __float2half_rn(v1);
                }
            }
        }
    }
}

// ---------------- Kernel 2: fp16 m16n8k16 GEMM, BK=32, 3-stage cp.async ----------------
#define GSTAGE 3
#define GSTRIDE_H (128*40)                    // halves per operand per stage
#define G_SMEM_BYTES (GSTAGE * 2 * GSTRIDE_H * 2)   // 61440 B; x2 CTAs = 120 KB

__global__ __launch_bounds__(256, 2) void gemm_pre_kernel()
{
    extern __shared__ __align__(16) __half smh[];
    __half* sA = smh;
    __half* sB = smh + GSTAGE * GSTRIDE_H;

    const int tid  = threadIdx.x;
    const int lane = tid & 31;
    const int wid  = tid >> 5;
    const int lr = lane >> 2, lc = lane & 3;
    const int wm = wid & 1;
    const int wn = wid >> 1;
    const int row0 = blockIdx.y * 128;
    const int col0 = blockIdx.x * 128;

    const unsigned baseA = smem_u32(sA);
    const unsigned baseB = smem_u32(sB);

    float acc[4][4][4];
    #pragma unroll
    for (int mt = 0; mt < 4; mt++)
        #pragma unroll
        for (int nt = 0; nt < 4; nt++)
            #pragma unroll
            for (int r = 0; r < 4; r++) acc[mt][nt][r] = 0.f;

    #define G_ISSUE(s, kt)                                                              \
    {                                                                                   \
        _Pragma("unroll")                                                               \
        for (int c = 0; c < 4; c++) {                                                   \
            int idx = tid + c * 256;                                                    \
            int isB = idx >> 9;                                                         \
            int m = (idx & 511) >> 2, kq = (idx & 3) * 8;                               \
            const __half* src = (isB ? g_wih + (size_t)(col0 + m) * NFLAT               \
                                     : g_feat + (size_t)(row0 + m) * NFLAT)             \
                                + (kt) + kq;                                            \
            unsigned dst = (isB ? baseB : baseA)                                        \
                           + ((s) * GSTRIDE_H + m * 40 + kq) * 2;                       \
            asm volatile("cp.async.cg.shared.global [%0], [%1], 16;"                    \
                         :: "r"(dst), "l"(src));                                        \
        }                                                                               \
    }

    G_ISSUE(0, 0);
    asm volatile("cp.async.commit_group;");
    G_ISSUE(1, 32);
    asm volatile("cp.async.commit_group;");

    const int NIT = NFLAT / 32;   // 32
    for (int it = 0; it < NIT; it++) {
        const int s = it % GSTAGE;
        asm volatile("cp.async.wait_group 1;");
        __syncthreads();
        if (it + 2 < NIT) {
            G_ISSUE((it + 2) % GSTAGE, (it + 2) * 32);
        }
        asm volatile("cp.async.commit_group;");

        const __half* pA = sA + s * GSTRIDE_H;
        const __half* pB = sB + s * GSTRIDE_H;
        #pragma unroll
        for (int ks = 0; ks < 2; ks++) {
            const int k0 = ks * 16;
            unsigned a[4][4], b[4][2];
            #pragma unroll
            for (int mt = 0; mt < 4; mt++) {
                int m0 = wm * 64 + mt * 16;
                a[mt][0] = *(const unsigned*)&pA[(m0 + lr    ) * 40 + k0 + 2*lc    ];
                a[mt][1] = *(const unsigned*)&pA[(m0 + lr + 8) * 40 + k0 + 2*lc    ];
                a[mt][2] = *(const unsigned*)&pA[(m0 + lr    ) * 40 + k0 + 2*lc + 8];
                a[mt][3] = *(const unsigned*)&pA[(m0 + lr + 8) * 40 + k0 + 2*lc + 8];
            }
            #pragma unroll
            for (int nt = 0; nt < 4; nt++) {
                int n0 = wn * 32 + nt * 8;
                b[nt][0] = *(const unsigned*)&pB[(n0 + lr) * 40 + k0 + 2*lc    ];
                b[nt][1] = *(const unsigned*)&pB[(n0 + lr) * 40 + k0 + 2*lc + 8];
            }
            #pragma unroll
            for (int mt = 0; mt < 4; mt++)
                #pragma unroll
                for (int nt = 0; nt < 4; nt++) {
                    asm volatile(
                        "mma.sync.aligned.m16n8k16.row.col.f32.f16.f16.f32 "
                        "{%0,%1,%2,%3}, {%4,%5,%6,%7}, {%8,%9}, {%0,%1,%2,%3};\n"
                        : "+f"(acc[mt][nt][0]), "+f"(acc[mt][nt][1]),
                          "+f"(acc[mt][nt][2]), "+f"(acc[mt][nt][3])
                        : "r"(a[mt][0]), "r"(a[mt][1]), "r"(a[mt][2]), "r"(a[mt][3]),
                          "r"(b[nt][0]), "r"(b[nt][1]));
                }
        }
    }

    float bb0[4], bb1[4];
    #pragma unroll
    for (int nt = 0; nt < 4; nt++) {
        int col = col0 + wn * 32 + nt * 8 + 2 * lc;
        bb0[nt] = g_bias[col];
        bb1[nt] = g_bias[col + 1];
    }
    #pragma unroll
    for (int mt = 0; mt < 4; mt++) {
        int r0 = row0 + wm * 64 + mt * 16 + lr;
        #pragma unroll
        for (int nt = 0; nt < 4; nt++) {
            int col = col0 + wn * 32 + nt * 8 + 2 * lc;
            *(float2*)&g_pre[(size_t)r0 * G4 + col] =
                make_float2(acc[mt][nt][0] + bb0[nt], acc[mt][nt][1] + bb1[nt]);
            *(float2*)&g_pre[(size_t)(r0 + 8) * G4 + col] =
                make_float2(acc[mt][nt][2] + bb0[nt], acc[mt][nt][3] + bb1[nt]);
        }
    }
}

// ---------------- Kernel 3: persistent LSTM + fused heads (R11-exact) ----------------
#define RC 64
__global__ __launch_bounds__(512, 1) void lstm_kernel(
    const float* __restrict__ done,
    const float* __restrict__ h0, const float* __restrict__ c0,
    const float* __restrict__ w_hh,
    const float* __restrict__ aw, const float* __restrict__ ab,
    const float* __restrict__ cw, const float* __restrict__ cb,
    float* __restrict__ out,
    float* __restrict__ hT, float* __restrict__ cT)
{
    __shared__ float hs[2][128];
    __shared__ float cs[2][128];
    __shared__ float gs[2][512];
    __shared__ float ho[2][2][128];
    __shared__ float hw[8][128];
    __shared__ float hb[8];

    const int tid = threadIdx.x;
    const int b0  = blockIdx.x * 2;

    if (tid < 256) {
        int r = tid >> 7, u = tid & 127;
        float m = 1.f - done[b0 + r];
        hs[r][u] = h0[(b0 + r) * HID + u] * m;
        cs[r][u] = c0[(b0 + r) * HID + u] * m;
    }
    for (int i = tid; i < 8 * 128; i += 512) {
        int row = i >> 7, u = i & 127;
        hw[row][u] = (row < NA) ? aw[i] : cw[u];
    }
    if (tid < NA) hb[tid] = ab[tid];
    if (tid == NA) hb[NA] = cb[0];

    const float* wrow = w_hh + (size_t)tid * HID;
    float wc[RC];
    #pragma unroll
    for (int k = 0; k < RC; k++) wc[k] = wrow[k];
    __syncthreads();

    float a0 = g_pre[(size_t)b0 * G4 + tid];
    float a1 = g_pre[(size_t)(b0 + 1) * G4 + tid];

    for (int t = 0; t < TT; t++) {
        #pragma unroll
        for (int k = 0; k < RC; k++) {
            float w = wc[k];
            a0 = fmaf(w, hs[0][k], a0);
            a1 = fmaf(w, hs[1][k], a1);
        }
        #pragma unroll
        for (int k = RC; k < HID; k += 4) {
            float4 wv = *(const float4*)(wrow + k);
            a0 = fmaf(wv.x, hs[0][k], a0);   a0 = fmaf(wv.y, hs[0][k+1], a0);
            a0 = fmaf(wv.z, hs[0][k+2], a0); a0 = fmaf(wv.w, hs[0][k+3], a0);
            a1 = fmaf(wv.x, hs[1][k], a1);   a1 = fmaf(wv.y, hs[1][k+1], a1);
            a1 = fmaf(wv.z, hs[1][k+2], a1); a1 = fmaf(wv.w, hs[1][k+3], a1);
        }
        gs[0][tid] = a0;
        gs[1][tid] = a1;

        if (t + 1 < TT) {
            a0 = g_pre[((size_t)((t + 1) * BB + b0    )) * G4 + tid];
            a1 = g_pre[((size_t)((t + 1) * BB + b0 + 1)) * G4 + tid];
        }
        __syncthreads();

        if (tid < 256) {
            int r = tid >> 7, u = tid & 127;
            float ig = fast_sigmoid(gs[r][u]);
            float fg = fast_sigmoid(gs[r][128 + u]);
            float gg = fast_tanh(gs[r][256 + u]);
            float og = fast_sigmoid(gs[r][384 + u]);
            float c = fg * cs[r][u] + ig * gg;
            float h = og * fast_tanh(c);
            ho[t & 1][r][u] = h;
            float m = (t + 1 < TT) ? (1.f - done[(t + 1) * BB + b0 + r]) : 1.f;
            cs[r][u] = c * m;
            hs[r][u] = h * m;
        } else if (t > 0) {
            int tid2 = tid - 256;
            int r = tid2 >> 7, q = tid2 & 127;
            int col = q >> 4, seg = q & 15;
            const float* hv = ho[(t - 1) & 1][r] + seg * 8;
            const float* wv = hw[col] + seg * 8;
            float p = 0.f;
            #pragma unroll
            for (int j = 0; j < 8; j++) p = fmaf(hv[j], wv[j], p);
            #pragma unroll
            for (int off = 8; off >= 1; off >>= 1)
                p += __shfl_xor_sync(0xffffffffu, p, off);
            if (seg == 0)
                out[(size_t)((t - 1) * BB + b0 + r) * 8 + col] = p + hb[col];
        }
        __syncthreads();
    }

    if (tid < 256) {
        int r = tid >> 7, q = tid & 127;
        int col = q >> 4, seg = q & 15;
        const float* hv = ho[(TT - 1) & 1][r] + seg * 8;
        const float* wv = hw[col] + seg * 8;
        float p = 0.f;
        #pragma unroll
        for (int j = 0; j < 8; j++) p = fmaf(hv[j], wv[j], p);
        #pragma unroll
        for (int off = 8; off >= 1; off >>= 1)
            p += __shfl_xor_sync(0xffffffffu, p, off);
        if (seg == 0)
            out[(size_t)((TT - 1) * BB + b0 + r) * 8 + col] = p + hb[col];
    }

    if (tid < 256) {
        int r = tid >> 7, u = tid & 127;
        hT[(b0 + r) * HID + u] = hs[r][u];
        cT[(b0 + r) * HID + u] = cs[r][u];
    }
}

// ---------------- launch ----------------
extern "C" void kernel_launch(void* const* d_in, const int* in_sizes, int n_in,
                              void* d_out, int out_size)
{
    const float* obs   = (const float*)d_in[0];
    const float* done  = (const float*)d_in[1];
    const float* h0    = (const float*)d_in[2];
    const float* c0    = (const float*)d_in[3];
    const float* w1    = (const float*)d_in[4];
    const float* b1    = (const float*)d_in[5];
    const float* w2    = (const float*)d_in[6];
    const float* b2    = (const float*)d_in[7];
    const float* w3    = (const float*)d_in[8];
    const float* b3    = (const float*)d_in[9];
    const float* w_ih  = (const float*)d_in[10];
    const float* w_hh  = (const float*)d_in[11];
    const float* b_ih  = (const float*)d_in[12];
    const float* b_hh  = (const float*)d_in[13];
    const float* aw    = (const float*)d_in[14];
    const float* ab    = (const float*)d_in[15];
    const float* cw    = (const float*)d_in[16];
    const float* cb    = (const float*)d_in[17];

    float* out = (float*)d_out;                    // [N, 8]
    float* hT  = out + (size_t)NN * 8;             // [B, HID]
    float* cT  = hT + (size_t)BB * HID;            // [B, HID]

    static bool attr_done = false;
    if (!attr_done) {
        cudaFuncSetAttribute(conv_feat_kernel,
                             cudaFuncAttributeMaxDynamicSharedMemorySize,
                             CV_SMEM_BYTES);
        cudaFuncSetAttribute(gemm_pre_kernel,
                             cudaFuncAttributeMaxDynamicSharedMemorySize,
                             G_SMEM_BYTES);
        attr_done = true;
    }

    prep_kernel<<<(G4 * NFLAT / 4 + 255) / 256, 256>>>(w_ih, b_ih, b_hh);

    conv_feat_kernel<<<NN / 4, 256, CV_SMEM_BYTES>>>(obs, w1, b1, w2, b2, w3, b3);

    dim3 ggrid(G4 / 128, NN / 128);
    gemm_pre_kernel<<<ggrid, 256, G_SMEM_BYTES>>>();

    lstm_kernel<<<BB / 2, 512>>>(done, h0, c0, w_hh, aw, ab, cw, cb, out, hT, cT);
}

// round 15
// speedup vs baseline: 1.7468x; 1.1590x over previous
#include <cuda_runtime.h>
#include <cuda_fp16.h>
#include <cuda_bf16.h>
#include <math.h>
#include <stdint.h>

// Problem dims
#define TT   128
#define BB   256
#define NN   (TT*BB)        // 32768
#define HID  128
#define G4   512            // 4*HID
#define NFLAT 1024
#define NA   7

// R10: harness emits compute_103 PTX -> no tcgen05; mma.sync is the ceiling.
// R12/R13: DVFS throttle explains R12's regression; fp16 GEMM is a real win.

// ---------------- scratch (device globals, no allocation) ----------------
__device__ __align__(16) __half g_feat[NN * NFLAT];  // fp16 feat (67 MB)
__device__ __align__(16) float  g_pre [NN * G4];
__device__ __align__(16) __half g_wih [G4 * NFLAT];  // fp16 weights (1 MB)
__device__ __align__(16) __half g_w3h [64 * 128];    // fp16 conv3 weights
__device__ __align__(16) float  g_bias[G4];

__device__ __forceinline__ unsigned smem_u32(const void* p) {
    unsigned r;
    asm("{ .reg .u64 t; cvta.to.shared.u64 t, %1; cvt.u32.u64 %0, t; }" : "=r"(r) : "l"(p));
    return r;
}
// MUFU-based tanh, overflow-safe
__device__ __forceinline__ float fast_tanh(float x) {
    float t = __expf(-2.f * fabsf(x));
    float r = __fdividef(1.f - t, 1.f + t);
    return copysignf(r, x);
}
__device__ __forceinline__ float fast_sigmoid(float x) {
    return __fdividef(1.f, 1.f + __expf(-x));
}

// ---------------- Kernel 0: prep (fp16 weights + fused bias) ----------------
__global__ __launch_bounds__(256) void prep_kernel(
    const float* __restrict__ wih, const float* __restrict__ w3,
    const float* __restrict__ bih, const float* __restrict__ bhh)
{
    int i = blockIdx.x * 256 + threadIdx.x;
    if (i < G4 * NFLAT / 4) {
        float4 v = *(const float4*)&wih[i * 4];
        __half2 h01 = __floats2half2_rn(v.x, v.y);
        __half2 h23 = __floats2half2_rn(v.z, v.w);
        uint2 pk;
        pk.x = *(unsigned*)&h01;
        pk.y = *(unsigned*)&h23;
        *(uint2*)&g_wih[i * 4] = pk;
    }
    if (i < 64 * 128 / 4) {
        float4 v = *(const float4*)&w3[i * 4];
        __half2 h01 = __floats2half2_rn(v.x, v.y);
        __half2 h23 = __floats2half2_rn(v.z, v.w);
        uint2 pk;
        pk.x = *(unsigned*)&h01;
        pk.y = *(unsigned*)&h23;
        *(uint2*)&g_w3h[i * 4] = pk;
    }
    if (i < G4) g_bias[i] = bih[i] + bhh[i];
}

// ---------------- Kernel 1: conv stack, 8 samples/block; conv3 fp16 mma ----------------
// smem (float offsets unless noted):
//   XS 0..1176, C1 1176 (stride 577), C2 5792 (stride 801), W2 12200 (2048)
//   A halves @byte 56992: 128 rows x 136 stride   (34816 B)
//   B halves @byte 91808:  64 rows x 136 stride   (17408 B)
#define CV8_XS 0
#define CV8_C1 1176
#define CV8_S1 577
#define CV8_C2 5792
#define CV8_S2 801
#define CV8_W2 12200
#define CV8_AH_BYTE 56992
#define CV8_BH_BYTE 91808
#define CV8_SMEM_BYTES 109216   // x2 CTAs = 218432 < 228 KB

__global__ __launch_bounds__(256) void conv_feat_kernel(
    const float* __restrict__ obs,
    const float* __restrict__ w1, const float* __restrict__ b1,
    const float* __restrict__ w2, const float* __restrict__ b2,
    const float* __restrict__ b3)
{
    extern __shared__ __align__(16) float sm[];
    __half* Ah = (__half*)((char*)sm + CV8_AH_BYTE);
    __half* Bh = (__half*)((char*)sm + CV8_BH_BYTE);
    const int tid = threadIdx.x;
    const int n0 = blockIdx.x * 8;

    // stage conv2 weights (float4) + conv3 fp16 weights (uint4, pre-converted)
    {
        const float4* s2 = (const float4*)w2;
        float4* d2 = (float4*)(sm + CV8_W2);
        for (int i = tid; i < 32*16; i += 256) d2[i] = s2[i];
        for (int i = tid; i < 1024; i += 256) {           // 64 rows x 8 chunks of 8 halves
            int row = i >> 4, seg = i & 15;
            *(uint4*)&Bh[row * 136 + seg * 8] = *(const uint4*)&g_w3h[row * 128 + seg * 8];
        }
    }
    // load obs for 8 samples, NHWC -> CHW
    for (int i = tid; i < 8*147; i += 256) {
        int s = i / 147, r = i % 147;
        int h = r / 21, q = r % 21, w = q / 3, c = q % 3;
        sm[CV8_XS + s*147 + c*49 + h*7 + w] = obs[(size_t)n0 * 147 + i];
    }
    __syncthreads();

    // conv1: 16 x 6x6, 3ch 2x2 (fp32), 8 samples
    for (int i = tid; i < 8*576; i += 256) {
        int s = i / 576, r = i % 576;
        int o = r / 36, q = r % 36, y = q / 6, x = q % 6;
        float acc = __ldg(&b1[o]);
        #pragma unroll
        for (int c = 0; c < 3; c++) {
            float4 wv = *(const float4*)&w1[(o*3 + c) * 4];
            const float* xb = sm + CV8_XS + s*147 + c*49 + y*7 + x;
            acc += xb[0] * wv.x + xb[1] * wv.y + xb[7] * wv.z + xb[8] * wv.w;
        }
        sm[CV8_C1 + s*CV8_S1 + o*36 + y*6 + x] = fmaxf(acc, 0.f);
    }
    __syncthreads();

    // conv2: 32 x 5x5, 16ch 2x2 (fp32). thread=(pos,sample), all 32 o in regs.
    if (tid < 200) {
        int pos = tid >> 3, s = tid & 7;
        int y = pos / 5, x = pos % 5;
        float acc[32];
        #pragma unroll
        for (int o = 0; o < 32; o++) acc[o] = __ldg(&b2[o]);
        const float4* w2v = (const float4*)(sm + CV8_W2);
        #pragma unroll 4
        for (int c = 0; c < 16; c++) {
            const float* xb = sm + CV8_C1 + s*CV8_S1 + c*36 + y*6 + x;
            float aa = xb[0], ab = xb[1], ac = xb[6], ad = xb[7];
            #pragma unroll
            for (int o = 0; o < 32; o++) {
                float4 wv = w2v[o*16 + c];                // warp-broadcast
                acc[o] += aa*wv.x + ab*wv.y + ac*wv.z + ad*wv.w;
            }
        }
        #pragma unroll
        for (int o = 0; o < 32; o++)
            sm[CV8_C2 + s*CV8_S2 + o*25 + pos] = fmaxf(acc[o], 0.f);
    }
    __syncthreads();

    // im2col -> fp16 A: row = s*16+pos, col = c*4 + (dy*2+dx), stride 136
    for (int i = tid; i < 128*128; i += 256) {
        int row = i >> 7, col = i & 127;
        int s = row >> 4, pos = row & 15, y = pos >> 2, x = pos & 3;
        int c = col >> 2, j = col & 3, dy = j >> 1, dx = j & 1;
        float v = sm[CV8_C2 + s*CV8_S2 + c*25 + (y+dy)*5 + (x+dx)];
        Ah[row * 136 + col] = __float2half_rn(v);
    }
    __syncthreads();

    // conv3 mma: [128x64] = A[128x128] @ B^T, m16n8k16 fp16
    // 8 warps: wm 0..3 (M 32 each), wn 0..1 (N 32 each); warp tile 32x32.
    {
        const int lane = tid & 31, wid = tid >> 5;
        const int lr = lane >> 2, lc = lane & 3;
        const int wm = wid & 3, wn = wid >> 2;

        float acc[2][4][4];
        #pragma unroll
        for (int mt = 0; mt < 2; mt++)
            #pragma unroll
            for (int nt = 0; nt < 4; nt++)
                #pragma unroll
                for (int r = 0; r < 4; r++) acc[mt][nt][r] = 0.f;

        #pragma unroll
        for (int ks = 0; ks < 8; ks++) {
            const int k0 = ks * 16;
            unsigned a[2][4], b[4][2];
            #pragma unroll
            for (int mt = 0; mt < 2; mt++) {
                int m0 = wm * 32 + mt * 16;
                a[mt][0] = *(const unsigned*)&Ah[(m0 + lr    ) * 136 + k0 + 2*lc    ];
                a[mt][1] = *(const unsigned*)&Ah[(m0 + lr + 8) * 136 + k0 + 2*lc    ];
                a[mt][2] = *(const unsigned*)&Ah[(m0 + lr    ) * 136 + k0 + 2*lc + 8];
                a[mt][3] = *(const unsigned*)&Ah[(m0 + lr + 8) * 136 + k0 + 2*lc + 8];
            }
            #pragma unroll
            for (int nt = 0; nt < 4; nt++) {
                int nr = wn * 32 + nt * 8;
                b[nt][0] = *(const unsigned*)&Bh[(nr + lr) * 136 + k0 + 2*lc    ];
                b[nt][1] = *(const unsigned*)&Bh[(nr + lr) * 136 + k0 + 2*lc + 8];
            }
            #pragma unroll
            for (int mt = 0; mt < 2; mt++)
                #pragma unroll
                for (int nt = 0; nt < 4; nt++) {
                    asm volatile(
                        "mma.sync.aligned.m16n8k16.row.col.f32.f16.f16.f32 "
                        "{%0,%1,%2,%3}, {%4,%5,%6,%7}, {%8,%9}, {%0,%1,%2,%3};\n"
                        : "+f"(acc[mt][nt][0]), "+f"(acc[mt][nt][1]),
                          "+f"(acc[mt][nt][2]), "+f"(acc[mt][nt][3])
                        : "r"(a[mt][0]), "r"(a[mt][1]), "r"(a[mt][2]), "r"(a[mt][3]),
                          "r"(b[nt][0]), "r"(b[nt][1]));
                }
        }

        // epilogue: bias + relu -> fp16 g_feat[(n0+s)*1024 + o*16 + pos]
        #pragma unroll
        for (int mt = 0; mt < 2; mt++) {
            #pragma unroll
            for (int nt = 0; nt < 4; nt++) {
                int o = wn * 32 + nt * 8 + 2 * lc;
                float bo0 = __ldg(&b3[o]), bo1 = __ldg(&b3[o + 1]);
                #pragma unroll
                for (int rr = 0; rr < 2; rr++) {
                    int row = wm * 32 + mt * 16 + lr + rr * 8;
                    int s = row >> 4, pos = row & 15;
                    __half* fo = g_feat + (size_t)(n0 + s) * NFLAT;
                    float v0 = fmaxf(acc[mt][nt][rr * 2    ] + bo0, 0.f);
                    float v1 = fmaxf(acc[mt][nt][rr * 2 + 1] + bo1, 0.f);
                    fo[o * 16 + pos]       = __float2half_rn(v0);
                    fo[(o + 1) * 16 + pos] = __float2half_rn(v1);
                }
            }
        }
    }
}

// ---------------- Kernel 2: fp16 m16n8k16 GEMM, BK=32, 3-stage cp.async (R13-exact) ----------------
#define GSTAGE 3
#define GSTRIDE_H (128*40)
#define G_SMEM_BYTES (GSTAGE * 2 * GSTRIDE_H * 2)   // 61440 B; x2 CTAs = 120 KB

__global__ __launch_bounds__(256, 2) void gemm_pre_kernel()
{
    extern __shared__ __align__(16) __half smh[];
    __half* sA = smh;
    __half* sB = smh + GSTAGE * GSTRIDE_H;

    const int tid  = threadIdx.x;
    const int lane = tid & 31;
    const int wid  = tid >> 5;
    const int lr = lane >> 2, lc = lane & 3;
    const int wm = wid & 1;
    const int wn = wid >> 1;
    const int row0 = blockIdx.y * 128;
    const int col0 = blockIdx.x * 128;

    const unsigned baseA = smem_u32(sA);
    const unsigned baseB = smem_u32(sB);

    float acc[4][4][4];
    #pragma unroll
    for (int mt = 0; mt < 4; mt++)
        #pragma unroll
        for (int nt = 0; nt < 4; nt++)
            #pragma unroll
            for (int r = 0; r < 4; r++) acc[mt][nt][r] = 0.f;

    #define G_ISSUE(s, kt)                                                              \
    {                                                                                   \
        _Pragma("unroll")                                                               \
        for (int c = 0; c < 4; c++) {                                                   \
            int idx = tid + c * 256;                                                    \
            int isB = idx >> 9;                                                         \
            int m = (idx & 511) >> 2, kq = (idx & 3) * 8;                               \
            const __half* src = (isB ? g_wih + (size_t)(col0 + m) * NFLAT               \
                                     : g_feat + (size_t)(row0 + m) * NFLAT)             \
                                + (kt) + kq;                                            \
            unsigned dst = (isB ? baseB : baseA)                                        \
                           + ((s) * GSTRIDE_H + m * 40 + kq) * 2;                       \
            asm volatile("cp.async.cg.shared.global [%0], [%1], 16;"                    \
                         :: "r"(dst), "l"(src));                                        \
        }                                                                               \
    }

    G_ISSUE(0, 0);
    asm volatile("cp.async.commit_group;");
    G_ISSUE(1, 32);
    asm volatile("cp.async.commit_group;");

    const int NIT = NFLAT / 32;   // 32
    for (int it = 0; it < NIT; it++) {
        const int s = it % GSTAGE;
        asm volatile("cp.async.wait_group 1;");
        __syncthreads();
        if (it + 2 < NIT) {
            G_ISSUE((it + 2) % GSTAGE, (it + 2) * 32);
        }
        asm volatile("cp.async.commit_group;");

        const __half* pA = sA + s * GSTRIDE_H;
        const __half* pB = sB + s * GSTRIDE_H;
        #pragma unroll
        for (int ks = 0; ks < 2; ks++) {
            const int k0 = ks * 16;
            unsigned a[4][4], b[4][2];
            #pragma unroll
            for (int mt = 0; mt < 4; mt++) {
                int m0 = wm * 64 + mt * 16;
                a[mt][0] = *(const unsigned*)&pA[(m0 + lr    ) * 40 + k0 + 2*lc    ];
                a[mt][1] = *(const unsigned*)&pA[(m0 + lr + 8) * 40 + k0 + 2*lc    ];
                a[mt][2] = *(const unsigned*)&pA[(m0 + lr    ) * 40 + k0 + 2*lc + 8];
                a[mt][3] = *(const unsigned*)&pA[(m0 + lr + 8) * 40 + k0 + 2*lc + 8];
            }
            #pragma unroll
            for (int nt = 0; nt < 4; nt++) {
                int n0 = wn * 32 + nt * 8;
                b[nt][0] = *(const unsigned*)&pB[(n0 + lr) * 40 + k0 + 2*lc    ];
                b[nt][1] = *(const unsigned*)&pB[(n0 + lr) * 40 + k0 + 2*lc + 8];
            }
            #pragma unroll
            for (int mt = 0; mt < 4; mt++)
                #pragma unroll
                for (int nt = 0; nt < 4; nt++) {
                    asm volatile(
                        "mma.sync.aligned.m16n8k16.row.col.f32.f16.f16.f32 "
                        "{%0,%1,%2,%3}, {%4,%5,%6,%7}, {%8,%9}, {%0,%1,%2,%3};\n"
                        : "+f"(acc[mt][nt][0]), "+f"(acc[mt][nt][1]),
                          "+f"(acc[mt][nt][2]), "+f"(acc[mt][nt][3])
                        : "r"(a[mt][0]), "r"(a[mt][1]), "r"(a[mt][2]), "r"(a[mt][3]),
                          "r"(b[nt][0]), "r"(b[nt][1]));
                }
        }
    }

    float bb0[4], bb1[4];
    #pragma unroll
    for (int nt = 0; nt < 4; nt++) {
        int col = col0 + wn * 32 + nt * 8 + 2 * lc;
        bb0[nt] = g_bias[col];
        bb1[nt] = g_bias[col + 1];
    }
    #pragma unroll
    for (int mt = 0; mt < 4; mt++) {
        int r0 = row0 + wm * 64 + mt * 16 + lr;
        #pragma unroll
        for (int nt = 0; nt < 4; nt++) {
            int col = col0 + wn * 32 + nt * 8 + 2 * lc;
            *(float2*)&g_pre[(size_t)r0 * G4 + col] =
                make_float2(acc[mt][nt][0] + bb0[nt], acc[mt][nt][1] + bb1[nt]);
            *(float2*)&g_pre[(size_t)(r0 + 8) * G4 + col] =
                make_float2(acc[mt][nt][2] + bb0[nt], acc[mt][nt][3] + bb1[nt]);
        }
    }
}

// ---------------- Kernel 3: persistent LSTM + fused heads (R13-exact) ----------------
#define RC 64
__global__ __launch_bounds__(512, 1) void lstm_kernel(
    const float* __restrict__ done,
    const float* __restrict__ h0, const float* __restrict__ c0,
    const float* __restrict__ w_hh,
    const float* __restrict__ aw, const float* __restrict__ ab,
    const float* __restrict__ cw, const float* __restrict__ cb,
    float* __restrict__ out,
    float* __restrict__ hT, float* __restrict__ cT)
{
    __shared__ float hs[2][128];
    __shared__ float cs[2][128];
    __shared__ float gs[2][512];
    __shared__ float ho[2][2][128];
    __shared__ float hw[8][128];
    __shared__ float hb[8];

    const int tid = threadIdx.x;
    const int b0  = blockIdx.x * 2;

    if (tid < 256) {
        int r = tid >> 7, u = tid & 127;
        float m = 1.f - done[b0 + r];
        hs[r][u] = h0[(b0 + r) * HID + u] * m;
        cs[r][u] = c0[(b0 + r) * HID + u] * m;
    }
    for (int i = tid; i < 8 * 128; i += 512) {
        int row = i >> 7, u = i & 127;
        hw[row][u] = (row < NA) ? aw[i] : cw[u];
    }
    if (tid < NA) hb[tid] = ab[tid];
    if (tid == NA) hb[NA] = cb[0];

    const float* wrow = w_hh + (size_t)tid * HID;
    float wc[RC];
    #pragma unroll
    for (int k = 0; k < RC; k++) wc[k] = wrow[k];
    __syncthreads();

    float a0 = g_pre[(size_t)b0 * G4 + tid];
    float a1 = g_pre[(size_t)(b0 + 1) * G4 + tid];

    for (int t = 0; t < TT; t++) {
        #pragma unroll
        for (int k = 0; k < RC; k++) {
            float w = wc[k];
            a0 = fmaf(w, hs[0][k], a0);
            a1 = fmaf(w, hs[1][k], a1);
        }
        #pragma unroll
        for (int k = RC; k < HID; k += 4) {
            float4 wv = *(const float4*)(wrow + k);
            a0 = fmaf(wv.x, hs[0][k], a0);   a0 = fmaf(wv.y, hs[0][k+1], a0);
            a0 = fmaf(wv.z, hs[0][k+2], a0); a0 = fmaf(wv.w, hs[0][k+3], a0);
            a1 = fmaf(wv.x, hs[1][k], a1);   a1 = fmaf(wv.y, hs[1][k+1], a1);
            a1 = fmaf(wv.z, hs[1][k+2], a1); a1 = fmaf(wv.w, hs[1][k+3], a1);
        }
        gs[0][tid] = a0;
        gs[1][tid] = a1;

        if (t + 1 < TT) {
            a0 = g_pre[((size_t)((t + 1) * BB + b0    )) * G4 + tid];
            a1 = g_pre[((size_t)((t + 1) * BB + b0 + 1)) * G4 + tid];
        }
        __syncthreads();

        if (tid < 256) {
            int r = tid >> 7, u = tid & 127;
            float ig = fast_sigmoid(gs[r][u]);
            float fg = fast_sigmoid(gs[r][128 + u]);
            float gg = fast_tanh(gs[r][256 + u]);
            float og = fast_sigmoid(gs[r][384 + u]);
            float c = fg * cs[r][u] + ig * gg;
            float h = og * fast_tanh(c);
            ho[t & 1][r][u] = h;
            float m = (t + 1 < TT) ? (1.f - done[(t + 1) * BB + b0 + r]) : 1.f;
            cs[r][u] = c * m;
            hs[r][u] = h * m;
        } else if (t > 0) {
            int tid2 = tid - 256;
            int r = tid2 >> 7, q = tid2 & 127;
            int col = q >> 4, seg = q & 15;
            const float* hv = ho[(t - 1) & 1][r] + seg * 8;
            const float* wv = hw[col] + seg * 8;
            float p = 0.f;
            #pragma unroll
            for (int j = 0; j < 8; j++) p = fmaf(hv[j], wv[j], p);
            #pragma unroll
            for (int off = 8; off >= 1; off >>= 1)
                p += __shfl_xor_sync(0xffffffffu, p, off);
            if (seg == 0)
                out[(size_t)((t - 1) * BB + b0 + r) * 8 + col] = p + hb[col];
        }
        __syncthreads();
    }

    if (tid < 256) {
        int r = tid >> 7, q = tid & 127;
        int col = q >> 4, seg = q & 15;
        const float* hv = ho[(TT - 1) & 1][r] + seg * 8;
        const float* wv = hw[col] + seg * 8;
        float p = 0.f;
        #pragma unroll
        for (int j = 0; j < 8; j++) p = fmaf(hv[j], wv[j], p);
        #pragma unroll
        for (int off = 8; off >= 1; off >>= 1)
            p += __shfl_xor_sync(0xffffffffu, p, off);
        if (seg == 0)
            out[(size_t)((TT - 1) * BB + b0 + r) * 8 + col] = p + hb[col];
    }

    if (tid < 256) {
        int r = tid >> 7, u = tid & 127;
        hT[(b0 + r) * HID + u] = hs[r][u];
        cT[(b0 + r) * HID + u] = cs[r][u];
    }
}

// ---------------- launch ----------------
extern "C" void kernel_launch(void* const* d_in, const int* in_sizes, int n_in,
                              void* d_out, int out_size)
{
    const float* obs   = (const float*)d_in[0];
    const float* done  = (const float*)d_in[1];
    const float* h0    = (const float*)d_in[2];
    const float* c0    = (const float*)d_in[3];
    const float* w1    = (const float*)d_in[4];
    const float* b1    = (const float*)d_in[5];
    const float* w2    = (const float*)d_in[6];
    const float* b2    = (const float*)d_in[7];
    const float* w3    = (const float*)d_in[8];
    const float* b3    = (const float*)d_in[9];
    const float* w_ih  = (const float*)d_in[10];
    const float* w_hh  = (const float*)d_in[11];
    const float* b_ih  = (const float*)d_in[12];
    const float* b_hh  = (const float*)d_in[13];
    const float* aw    = (const float*)d_in[14];
    const float* ab    = (const float*)d_in[15];
    const float* cw    = (const float*)d_in[16];
    const float* cb    = (const float*)d_in[17];

    float* out = (float*)d_out;                    // [N, 8]
    float* hT  = out + (size_t)NN * 8;             // [B, HID]
    float* cT  = hT + (size_t)BB * HID;            // [B, HID]

    static bool attr_done = false;
    if (!attr_done) {
        cudaFuncSetAttribute(conv_feat_kernel,
                             cudaFuncAttributeMaxDynamicSharedMemorySize,
                             CV8_SMEM_BYTES);
        cudaFuncSetAttribute(gemm_pre_kernel,
                             cudaFuncAttributeMaxDynamicSharedMemorySize,
                             G_SMEM_BYTES);
        attr_done = true;
    }

    prep_kernel<<<(G4 * NFLAT / 4 + 255) / 256, 256>>>(w_ih, w3, b_ih, b_hh);

    conv_feat_kernel<<<NN / 8, 256, CV8_SMEM_BYTES>>>(obs, w1, b1, w2, b2, b3);

    dim3 ggrid(G4 / 128, NN / 128);
    gemm_pre_kernel<<<ggrid, 256, G_SMEM_BYTES>>>();

    lstm_kernel<<<BB / 2, 512>>>(done, h0, c0, w_hh, aw, ab, cw, cb, out, hT, cT);
}